// round 1
// baseline (speedup 1.0000x reference)
#include <cuda_runtime.h>
#include <stdint.h>

// PHM embedding: out[tok, q*256 + j] = sum_k a[k,p,q] * s[k,i,j]
//   t = input[tok]; p = t / 12565; i = t % 12565
//   a: [4,4,4] (k,p,q) f32 ; s: [4,12565,256] f32 ; out: [16384,1024] f32
//
// Block = 256 threads = 4 tokens x 64 lanes; each lane owns one float4 (4 cols).

static constexpr int N_ROWS = 12565;   // VOCAB_PAD / 4
static constexpr int EV4    = 64;      // 256 f32 cols / 4 per float4
static constexpr int TOK_PER_BLK = 4;

__global__ void __launch_bounds__(256, 8)
phm_embed_kernel(const int* __restrict__ inp,
                 const float* __restrict__ a,
                 const float4* __restrict__ s,
                 float4* __restrict__ out,
                 int n_tok)
{
    const int lane = threadIdx.x & 63;       // j-vector within token
    const int tsub = threadIdx.x >> 6;       // token within block
    const int tok  = blockIdx.x * TOK_PER_BLK + tsub;
    if (tok >= n_tok) return;

    const int t = inp[tok];
    const int p = t / N_ROWS;                // compile-time magic divide
    const int i = t - p * N_ROWS;

    // Front-batch the 4 independent s-row loads (MLP=4).
    float4 sv0 = __ldg(&s[(0 * N_ROWS + i) * EV4 + lane]);
    float4 sv1 = __ldg(&s[(1 * N_ROWS + i) * EV4 + lane]);
    float4 sv2 = __ldg(&s[(2 * N_ROWS + i) * EV4 + lane]);
    float4 sv3 = __ldg(&s[(3 * N_ROWS + i) * EV4 + lane]);

    // a[k,p,q] = a[k*16 + p*4 + q]; 16 broadcast loads, L1/const-cached.
    const float* ap = a + p * 4;

    float4* outp = out + (size_t)tok * 256;  // 1024 f32 = 256 float4

#pragma unroll
    for (int q = 0; q < 4; q++) {
        const float c0 = __ldg(&ap[ 0 + q]);
        const float c1 = __ldg(&ap[16 + q]);
        const float c2 = __ldg(&ap[32 + q]);
        const float c3 = __ldg(&ap[48 + q]);
        float4 o;
        o.x = c0 * sv0.x + c1 * sv1.x + c2 * sv2.x + c3 * sv3.x;
        o.y = c0 * sv0.y + c1 * sv1.y + c2 * sv2.y + c3 * sv3.y;
        o.z = c0 * sv0.z + c1 * sv1.z + c2 * sv2.z + c3 * sv3.z;
        o.w = c0 * sv0.w + c1 * sv1.w + c2 * sv2.w + c3 * sv3.w;
        outp[q * EV4 + lane] = o;
    }
}

extern "C" void kernel_launch(void* const* d_in, const int* in_sizes, int n_in,
                              void* d_out, int out_size)
{
    const int*    inp = (const int*)d_in[0];    // [8,2048] int32
    const float*  a   = (const float*)d_in[1];  // [4,4,4]
    const float4* s   = (const float4*)d_in[2]; // [4,12565,256] f32 as float4
    float4*       out = (float4*)d_out;

    const int n_tok = in_sizes[0];              // 16384
    const int grid  = (n_tok + TOK_PER_BLK - 1) / TOK_PER_BLK;
    phm_embed_kernel<<<grid, 256>>>(inp, a, s, out, n_tok);
}